// round 12
// baseline (speedup 1.0000x reference)
#include <cuda_runtime.h>
#include <cuda_bf16.h>
#include <cstdint>

#define BB 2
#define HH 8
#define LL 2048
#define LT 1024
#define DM 512
#define DH 64

// ---------------- scratch (no allocations allowed) ----------------
__device__ float g_Qh[BB*HH*LL*DH];
__device__ float g_Kh[BB*HH*LL*DH];
__device__ float g_Vh[BB*HH*LL*DH];
__device__ float g_AO[BB*HH*LL*DH];
__device__ float g_coef[BB*LL];

__device__ __forceinline__ uint32_t f2tf32(float x) {
    uint32_t u;
    asm("cvt.rna.tf32.f32 %0, %1;" : "=r"(u) : "f"(x));
    return u;
}

__device__ __forceinline__ void mma_tf32(float d[4], const uint32_t a[4], const uint32_t b[2]) {
    asm volatile(
        "mma.sync.aligned.m16n8k8.row.col.f32.tf32.tf32.f32 "
        "{%0,%1,%2,%3}, {%4,%5,%6,%7}, {%8,%9}, {%0,%1,%2,%3};\n"
        : "+f"(d[0]), "+f"(d[1]), "+f"(d[2]), "+f"(d[3])
        : "r"(a[0]), "r"(a[1]), "r"(a[2]), "r"(a[3]), "r"(b[0]), "r"(b[1]));
}

// ---------------- coef: post-softmax reweighting per (b, pos) ----------------
__global__ void coef_kernel(const float* __restrict__ tm, const float* __restrict__ am,
                            float* __restrict__ coef) {
    __shared__ float red[256];
    __shared__ float s_tl;
    __shared__ float s_al;
    int b = blockIdx.x, tid = threadIdx.x;
    float tl = 0.f, al = 0.f;
    for (int i = tid; i < LT; i += 256) { tl += tm[b*LT + i]; al += am[b*LT + i]; }
    red[tid] = tl; __syncthreads();
    for (int s = 128; s > 0; s >>= 1) { if (tid < s) red[tid] += red[tid + s]; __syncthreads(); }
    if (tid == 0) s_tl = red[0];
    __syncthreads();
    red[tid] = al; __syncthreads();
    for (int s = 128; s > 0; s >>= 1) { if (tid < s) red[tid] += red[tid + s]; __syncthreads(); }
    if (tid == 0) s_al = red[0];
    __syncthreads();
    float tot = s_tl + s_al;
    float twf = tot / (2.f * s_tl);
    float awf = tot / (2.f * s_al);
    for (int i = tid; i < LT; i += 256) {
        coef[b*LL + i]      = tm[b*LT + i] * twf;
        coef[b*LL + LT + i] = am[b*LT + i] * awf;
    }
}

// ---------------- tf32 GEMM core geometry ----------------
// 128x64 block tile, BK=32, 256 threads (8 warps 4x2, warp 32x32).
#define GA_STR 136
#define GB_STR 73
#define GEMM_SMEM_BYTES ((2*32*GA_STR + 2*32*GB_STR) * 4)

// ---------------- merged QKV projection GEMM (blockIdx.z selects q/k/v) --------
__global__ __launch_bounds__(256, 2) void gemm_qkv(
        const float* __restrict__ xq, const float* __restrict__ xk,
        const float* __restrict__ xv,
        const float* __restrict__ wq, const float* __restrict__ wk,
        const float* __restrict__ wv,
        const float* __restrict__ bq, const float* __restrict__ bk,
        const float* __restrict__ bv,
        float* __restrict__ yq, float* __restrict__ yk, float* __restrict__ yv) {
    extern __shared__ uint32_t gsm[];
    uint32_t* As = gsm;                    // [2][32][136]
    uint32_t* Bs = gsm + 2*32*GA_STR;      // [2][32][73]
    int z = blockIdx.z;
    const float* X    = (z == 0) ? xq : (z == 1) ? xk : xv;
    const float* W    = (z == 0) ? wq : (z == 1) ? wk : wv;
    const float* bias = (z == 0) ? bq : (z == 1) ? bk : bv;
    float*       Y    = (z == 0) ? yq : (z == 1) ? yk : yv;

    int tid = threadIdx.x;
    int lane = tid & 31, warp = tid >> 5;
    int gid = lane >> 2, tig = lane & 3;
    int wm0 = (warp >> 1) * 32, wn0 = (warp & 1) * 32;
    int n0 = blockIdx.x * 64, m0 = blockIdx.y * 128;

    float acc[2][4][4];
    #pragma unroll
    for (int mt = 0; mt < 2; mt++)
        #pragma unroll
        for (int nt = 0; nt < 4; nt++)
            #pragma unroll
            for (int r = 0; r < 4; r++) acc[mt][nt][r] = 0.f;

    int ar = tid >> 1, ac = (tid & 1) * 16;
    int br = tid >> 2, bc = (tid & 3) * 8;
    int m = m0 + ar;
    const float* Wp = W + (size_t)(n0 + br)*DM + bc;

    float ra[16], rb[8];
    auto LD = [&](int k0) {
        const float* xp = X + (size_t)m*DM + k0 + ac;
        #pragma unroll
        for (int j = 0; j < 4; j++) {
            float4 v = *reinterpret_cast<const float4*>(xp + 4*j);
            ra[j*4+0] = v.x; ra[j*4+1] = v.y; ra[j*4+2] = v.z; ra[j*4+3] = v.w;
        }
        #pragma unroll
        for (int j = 0; j < 2; j++) {
            float4 v = *reinterpret_cast<const float4*>(Wp + k0 + 4*j);
            rb[j*4+0] = v.x; rb[j*4+1] = v.y; rb[j*4+2] = v.z; rb[j*4+3] = v.w;
        }
    };
    auto ST = [&](int st) {
        #pragma unroll
        for (int j = 0; j < 4; j++)
            #pragma unroll
            for (int e = 0; e < 4; e++)
                As[(size_t)(st*32 + ac + 4*j + e)*GA_STR + ar] = f2tf32(ra[j*4+e]);
        #pragma unroll
        for (int j = 0; j < 2; j++)
            #pragma unroll
            for (int e = 0; e < 4; e++)
                Bs[(size_t)(st*32 + bc + 4*j + e)*GB_STR + br] = f2tf32(rb[j*4+e]);
    };

    LD(0); ST(0); __syncthreads();
    for (int it = 0; it < 16; it++) {
        int st = it & 1;
        if (it < 15) LD((it+1)*32);
        #pragma unroll
        for (int kk = 0; kk < 32; kk += 8) {
            const uint32_t* Ab = As + (size_t)(st*32 + kk + tig)*GA_STR;
            uint32_t af[2][4];
            #pragma unroll
            for (int mt = 0; mt < 2; mt++) {
                int mi = wm0 + mt*16 + gid;
                af[mt][0] = Ab[mi];
                af[mt][1] = Ab[mi + 8];
                af[mt][2] = Ab[4*GA_STR + mi];
                af[mt][3] = Ab[4*GA_STR + mi + 8];
            }
            const uint32_t* Bb = Bs + (size_t)(st*32 + kk + tig)*GB_STR;
            #pragma unroll
            for (int nt = 0; nt < 4; nt++) {
                int ni = wn0 + nt*8 + gid;
                uint32_t bf[2] = { Bb[ni], Bb[4*GB_STR + ni] };
                mma_tf32(acc[0][nt], af[0], bf);
                mma_tf32(acc[1][nt], af[1], bf);
            }
        }
        if (it < 15) ST(st ^ 1);
        __syncthreads();
    }

    // scatter into [B,H,L,Dh]
    #pragma unroll
    for (int mt = 0; mt < 2; mt++) {
        #pragma unroll
        for (int nt = 0; nt < 4; nt++) {
            int r0 = m0 + wm0 + mt*16 + gid;
            int c0 = n0 + wn0 + nt*8 + 2*tig;
            float b0 = bias[c0], b1 = bias[c0+1];
            float2 v0 = make_float2(acc[mt][nt][0] + b0, acc[mt][nt][1] + b1);
            float2 v1 = make_float2(acc[mt][nt][2] + b0, acc[mt][nt][3] + b1);
            int bb = r0 >> 11, ll = r0 & 2047;
            int h = c0 >> 6, dd = c0 & 63;
            float* yp = Y + (((size_t)(bb*HH + h)*LL + ll)*DH + dd);
            *reinterpret_cast<float2*>(yp)        = v0;
            *reinterpret_cast<float2*>(yp + 8*DH) = v1;
        }
    }
}

// ---------------- output projection GEMM (gather from [B,H,L,Dh]) --------------
__global__ __launch_bounds__(256, 2) void gemm_out(const float* __restrict__ X,
        const float* __restrict__ W, const float* __restrict__ bias,
        float* __restrict__ Y) {
    extern __shared__ uint32_t gsm[];
    uint32_t* As = gsm;
    uint32_t* Bs = gsm + 2*32*GA_STR;
    int tid = threadIdx.x;
    int lane = tid & 31, warp = tid >> 5;
    int gid = lane >> 2, tig = lane & 3;
    int wm0 = (warp >> 1) * 32, wn0 = (warp & 1) * 32;
    int n0 = blockIdx.x * 64, m0 = blockIdx.y * 128;

    float acc[2][4][4];
    #pragma unroll
    for (int mt = 0; mt < 2; mt++)
        #pragma unroll
        for (int nt = 0; nt < 4; nt++)
            #pragma unroll
            for (int r = 0; r < 4; r++) acc[mt][nt][r] = 0.f;

    int ar = tid >> 1, ac = (tid & 1) * 16;
    int br = tid >> 2, bc = (tid & 3) * 8;
    int m = m0 + ar;
    int mb = m >> 11, ml = m & 2047;
    const float* Wp = W + (size_t)(n0 + br)*DM + bc;

    float ra[16], rb[8];
    auto LD = [&](int k0) {
        int kk4 = k0 + ac;   // multiple of 16; 16-elem span never crosses head
        const float* xp = X + (((size_t)(mb*HH + (kk4 >> 6))*LL + ml)*DH + (kk4 & 63));
        #pragma unroll
        for (int j = 0; j < 4; j++) {
            float4 v = *reinterpret_cast<const float4*>(xp + 4*j);
            ra[j*4+0] = v.x; ra[j*4+1] = v.y; ra[j*4+2] = v.z; ra[j*4+3] = v.w;
        }
        #pragma unroll
        for (int j = 0; j < 2; j++) {
            float4 v = *reinterpret_cast<const float4*>(Wp + k0 + 4*j);
            rb[j*4+0] = v.x; rb[j*4+1] = v.y; rb[j*4+2] = v.z; rb[j*4+3] = v.w;
        }
    };
    auto ST = [&](int st) {
        #pragma unroll
        for (int j = 0; j < 4; j++)
            #pragma unroll
            for (int e = 0; e < 4; e++)
                As[(size_t)(st*32 + ac + 4*j + e)*GA_STR + ar] = f2tf32(ra[j*4+e]);
        #pragma unroll
        for (int j = 0; j < 2; j++)
            #pragma unroll
            for (int e = 0; e < 4; e++)
                Bs[(size_t)(st*32 + bc + 4*j + e)*GB_STR + br] = f2tf32(rb[j*4+e]);
    };

    LD(0); ST(0); __syncthreads();
    for (int it = 0; it < 16; it++) {
        int st = it & 1;
        if (it < 15) LD((it+1)*32);
        #pragma unroll
        for (int kk = 0; kk < 32; kk += 8) {
            const uint32_t* Ab = As + (size_t)(st*32 + kk + tig)*GA_STR;
            uint32_t af[2][4];
            #pragma unroll
            for (int mt = 0; mt < 2; mt++) {
                int mi = wm0 + mt*16 + gid;
                af[mt][0] = Ab[mi];
                af[mt][1] = Ab[mi + 8];
                af[mt][2] = Ab[4*GA_STR + mi];
                af[mt][3] = Ab[4*GA_STR + mi + 8];
            }
            const uint32_t* Bb = Bs + (size_t)(st*32 + kk + tig)*GB_STR;
            #pragma unroll
            for (int nt = 0; nt < 4; nt++) {
                int ni = wn0 + nt*8 + gid;
                uint32_t bf[2] = { Bb[ni], Bb[4*GB_STR + ni] };
                mma_tf32(acc[0][nt], af[0], bf);
                mma_tf32(acc[1][nt], af[1], bf);
            }
        }
        if (it < 15) ST(st ^ 1);
        __syncthreads();
    }

    #pragma unroll
    for (int mt = 0; mt < 2; mt++) {
        #pragma unroll
        for (int nt = 0; nt < 4; nt++) {
            int r0 = m0 + wm0 + mt*16 + gid;
            int c0 = n0 + wn0 + nt*8 + 2*tig;
            float b0 = bias[c0], b1 = bias[c0+1];
            *reinterpret_cast<float2*>(Y + (size_t)r0*DM + c0) =
                make_float2(acc[mt][nt][0] + b0, acc[mt][nt][1] + b1);
            *reinterpret_cast<float2*>(Y + (size_t)(r0+8)*DM + c0) =
                make_float2(acc[mt][nt][2] + b0, acc[mt][nt][3] + b1);
        }
    }
}

// ---------------- tf32 flash attention, double-buffered K/V, shuffle-P ----------
// grid (L/128, B*H), 256 threads. Warp w owns q rows [w*16, w*16+16). 64-key tiles.
// P never touches SMEM: C-frag -> A-frag via quad shuffles. SMEM = 74.75 KB -> 2 CTA/SM.
#define KS_STR 72
#define ATT_SMEM_BYTES ((2*64*KS_STR*2 + 256) * 4)

__global__ __launch_bounds__(256, 2) void attn_tf32(const float* __restrict__ Qh,
        const float* __restrict__ Kh, const float* __restrict__ Vh,
        const float* __restrict__ tm, const float* __restrict__ am,
        const float* __restrict__ coef, float* __restrict__ Out) {
    extern __shared__ uint32_t smu[];
    uint32_t* Kd  = smu;                       // [2][d=64][col 72]
    uint32_t* Vd  = smu + 2*64*KS_STR;         // [2][kk=64][d 72]
    float* kmzS = (float*)(Vd + 2*64*KS_STR);  // [2][64]
    float* kcfS = kmzS + 128;                  // [2][64]
#define KS(st,d,c) Kd[(size_t)((st)*64 + (d))*KS_STR + (c)]
#define VS(st,r,c) Vd[(size_t)((st)*64 + (r))*KS_STR + (c)]

    int tid = threadIdx.x;
    int lane = tid & 31, warp = tid >> 5;
    int gid = lane >> 2, tig = lane & 3;
    int bh = blockIdx.y, b = bh >> 3;
    int q0 = blockIdx.x * 128;
    int qw = q0 + warp * 16;

    // Q fragments in registers (pre-scaled by 1/sqrt(64))
    uint32_t qf[8][4];
    const float* Qb = Qh + ((size_t)bh*LL + qw)*DH;
    #pragma unroll
    for (int kt = 0; kt < 8; kt++) {
        int c = kt*8 + tig;
        qf[kt][0] = f2tf32(Qb[(size_t)gid*DH     + c    ] * 0.125f);
        qf[kt][1] = f2tf32(Qb[(size_t)(gid+8)*DH + c    ] * 0.125f);
        qf[kt][2] = f2tf32(Qb[(size_t)gid*DH     + c + 4] * 0.125f);
        qf[kt][3] = f2tf32(Qb[(size_t)(gid+8)*DH + c + 4] * 0.125f);
    }
    int p0 = qw + gid, p1 = qw + gid + 8;
    float qz0 = (p0 < LT) ? tm[b*LT + p0] : am[b*LT + p0 - LT];
    float qz1 = (p1 < LT) ? tm[b*LT + p1] : am[b*LT + p1 - LT];

    float m0r = -1e30f, m1r = -1e30f, l0r = 0.f, l1r = 0.f;
    float o[8][4];
    #pragma unroll
    for (int nt = 0; nt < 8; nt++)
        #pragma unroll
        for (int r = 0; r < 4; r++) o[nt][r] = 0.f;

    int kcol = tid & 63, cgrp = (tid >> 6) * 16;   // K loader (transposed store)
    int vr = tid >> 2, vc = (tid & 3) * 16;        // V loader (direct store)
    const float* Kbase = Kh + (size_t)bh*LL*DH;
    const float* Vbase = Vh + (size_t)bh*LL*DH;

    float rbuf[16];          // reused for K-prefetch then V-prefetch
    float rmv = 0.f, rcv = 0.f;

    auto LDK = [&](int t0) {
        const float* p = Kbase + (size_t)(t0 + kcol)*DH + cgrp;
        #pragma unroll
        for (int j = 0; j < 4; j++) {
            float4 v = *reinterpret_cast<const float4*>(p + 4*j);
            rbuf[j*4+0] = v.x; rbuf[j*4+1] = v.y; rbuf[j*4+2] = v.z; rbuf[j*4+3] = v.w;
        }
    };
    auto STK = [&](int st) {
        #pragma unroll
        for (int j = 0; j < 4; j++)
            #pragma unroll
            for (int e = 0; e < 4; e++)
                KS(st, cgrp + 4*j + e, kcol) = f2tf32(rbuf[j*4+e]);
    };
    auto LDV = [&](int t0) {
        const float* p = Vbase + (size_t)(t0 + vr)*DH + vc;
        #pragma unroll
        for (int j = 0; j < 4; j++) {
            float4 v = *reinterpret_cast<const float4*>(p + 4*j);
            rbuf[j*4+0] = v.x; rbuf[j*4+1] = v.y; rbuf[j*4+2] = v.z; rbuf[j*4+3] = v.w;
        }
    };
    auto STV = [&](int st) {
        uint4* vd = reinterpret_cast<uint4*>(&VS(st, vr, vc));
        #pragma unroll
        for (int j = 0; j < 4; j++) {
            uint4 w;
            w.x = f2tf32(rbuf[j*4+0]); w.y = f2tf32(rbuf[j*4+1]);
            w.z = f2tf32(rbuf[j*4+2]); w.w = f2tf32(rbuf[j*4+3]);
            vd[j] = w;
        }
    };
    auto LDM = [&](int t0) {
        if (tid < 64) {
            int pos = t0 + tid;
            rmv = (pos < LT) ? tm[b*LT + pos] : am[b*LT + pos - LT];
            rcv = coef[b*LL + pos];
        }
    };
    auto STM = [&](int st) {
        if (tid < 64) { kmzS[st*64 + tid] = rmv; kcfS[st*64 + tid] = rcv; }
    };

    // prologue: fill buffer 0
    LDK(0); STK(0); LDV(0); STV(0); LDM(0); STM(0);
    __syncthreads();

    // shuffle-transpose lane mapping (C-frag of S -> A-frag of PV)
    int srcA = (lane & 28) | ((lane >> 1) & 1);   // = gid*4 + (tig>>1)
    int srcB = srcA | 2;                          // cols +4
    bool hi = (lane & 1);                         // = tig&1

    for (int i = 0; i < 32; i++) {
        int st = i & 1;
        bool pf = (i < 31);
        int t1 = (i + 1) * 64;
        if (pf) { LDK(t1); LDM(t1); }

        // S = Q @ K^T  (16 x 64 per warp)
        float s[8][4];
        #pragma unroll
        for (int nt = 0; nt < 8; nt++)
            #pragma unroll
            for (int r = 0; r < 4; r++) s[nt][r] = 0.f;
        #pragma unroll
        for (int kt = 0; kt < 8; kt++) {
            #pragma unroll
            for (int nt = 0; nt < 8; nt++) {
                uint32_t bf[2];
                bf[0] = KS(st, kt*8+tig,   nt*8+gid);
                bf[1] = KS(st, kt*8+tig+4, nt*8+gid);
                mma_tf32(s[nt], qf[kt], bf);
            }
        }
        if (pf) { STK(st ^ 1); STM(st ^ 1); }

        // dual mask
        const float* kmp = kmzS + st*64;
        const float* kcp = kcfS + st*64;
        #pragma unroll
        for (int nt = 0; nt < 8; nt++) {
            int c = nt*8 + 2*tig;
            float km0 = kmp[c], km1 = kmp[c+1];
            if (qz0 == 0.f || km0 == 0.f) s[nt][0] = -1e4f;
            if (qz0 == 0.f || km1 == 0.f) s[nt][1] = -1e4f;
            if (qz1 == 0.f || km0 == 0.f) s[nt][2] = -1e4f;
            if (qz1 == 0.f || km1 == 0.f) s[nt][3] = -1e4f;
        }

        // online softmax (rows gid / gid+8; quad lanes share a row)
        float rm0 = -1e30f, rm1 = -1e30f;
        #pragma unroll
        for (int nt = 0; nt < 8; nt++) {
            rm0 = fmaxf(rm0, fmaxf(s[nt][0], s[nt][1]));
            rm1 = fmaxf(rm1, fmaxf(s[nt][2], s[nt][3]));
        }
        rm0 = fmaxf(rm0, __shfl_xor_sync(0xffffffffu, rm0, 1));
        rm0 = fmaxf(rm0, __shfl_xor_sync(0xffffffffu, rm0, 2));
        rm1 = fmaxf(rm1, __shfl_xor_sync(0xffffffffu, rm1, 1));
        rm1 = fmaxf(rm1, __shfl_xor_sync(0xffffffffu, rm1, 2));
        float mn0 = fmaxf(m0r, rm0), mn1 = fmaxf(m1r, rm1);
        float rs0 = 0.f, rs1 = 0.f;
        #pragma unroll
        for (int nt = 0; nt < 8; nt++) {
            s[nt][0] = __expf(s[nt][0] - mn0);
            s[nt][1] = __expf(s[nt][1] - mn0);
            s[nt][2] = __expf(s[nt][2] - mn1);
            s[nt][3] = __expf(s[nt][3] - mn1);
            rs0 += s[nt][0] + s[nt][1];
            rs1 += s[nt][2] + s[nt][3];
        }
        rs0 += __shfl_xor_sync(0xffffffffu, rs0, 1);
        rs0 += __shfl_xor_sync(0xffffffffu, rs0, 2);
        rs1 += __shfl_xor_sync(0xffffffffu, rs1, 1);
        rs1 += __shfl_xor_sync(0xffffffffu, rs1, 2);
        float a0 = __expf(m0r - mn0), a1 = __expf(m1r - mn1);
        l0r = l0r*a0 + rs0; l1r = l1r*a1 + rs1;
        m0r = mn0; m1r = mn1;
        #pragma unroll
        for (int nt = 0; nt < 8; nt++) {
            o[nt][0] *= a0; o[nt][1] *= a0;
            o[nt][2] *= a1; o[nt][3] *= a1;
        }

        if (pf) LDV(t1);   // rbuf free again (STK done); overlap with PV below

        // O += (P*coef) @ V ; P A-frags built by shuffle from S C-frags
        #pragma unroll
        for (int kt = 0; kt < 8; kt++) {
            int c = kt*8 + 2*tig;
            float c0 = kcp[c], c1 = kcp[c+1];
            float pp0 = s[kt][0]*c0, pp1 = s[kt][1]*c1;
            float pp2 = s[kt][2]*c0, pp3 = s[kt][3]*c1;
            uint32_t af[4];
            {
                float v0 = __shfl_sync(0xffffffffu, pp0, srcA);
                float v1 = __shfl_sync(0xffffffffu, pp1, srcA);
                af[0] = f2tf32(hi ? v1 : v0);
                float v2 = __shfl_sync(0xffffffffu, pp2, srcA);
                float v3 = __shfl_sync(0xffffffffu, pp3, srcA);
                af[1] = f2tf32(hi ? v3 : v2);
                float w0 = __shfl_sync(0xffffffffu, pp0, srcB);
                float w1 = __shfl_sync(0xffffffffu, pp1, srcB);
                af[2] = f2tf32(hi ? w1 : w0);
                float w2 = __shfl_sync(0xffffffffu, pp2, srcB);
                float w3 = __shfl_sync(0xffffffffu, pp3, srcB);
                af[3] = f2tf32(hi ? w3 : w2);
            }
            #pragma unroll
            for (int nt = 0; nt < 8; nt++) {
                uint32_t bf[2];
                bf[0] = VS(st, kt*8+tig,   nt*8+gid);
                bf[1] = VS(st, kt*8+tig+4, nt*8+gid);
                mma_tf32(o[nt], af, bf);
            }
        }
        if (pf) STV(st ^ 1);
        __syncthreads();
    }

    float il0 = 1.f / l0r, il1 = 1.f / l1r;
    float* ob = Out + ((size_t)bh*LL + qw)*DH;
    #pragma unroll
    for (int nt = 0; nt < 8; nt++) {
        int c = nt*8 + 2*tig;
        *reinterpret_cast<float2*>(ob + (size_t)gid*DH + c) =
            make_float2(o[nt][0]*il0, o[nt][1]*il0);
        *reinterpret_cast<float2*>(ob + (size_t)(gid+8)*DH + c) =
            make_float2(o[nt][2]*il1, o[nt][3]*il1);
    }
}

extern "C" void kernel_launch(void* const* d_in, const int* in_sizes, int n_in,
                              void* d_out, int out_size) {
    const float* q  = (const float*)d_in[0];
    const float* k  = (const float*)d_in[1];
    const float* v  = (const float*)d_in[2];
    const float* tm = (const float*)d_in[3];
    const float* am = (const float*)d_in[4];
    // d_in[5] = n_head (constant 8)
    const float* wq = (const float*)d_in[6];
    const float* bq = (const float*)d_in[7];
    const float* wk = (const float*)d_in[8];
    const float* bk = (const float*)d_in[9];
    const float* wv = (const float*)d_in[10];
    const float* bv = (const float*)d_in[11];
    const float* wo = (const float*)d_in[12];
    const float* bo = (const float*)d_in[13];
    float* out = (float*)d_out;

    float *Qh, *Kh, *Vh, *AO, *coef;
    cudaGetSymbolAddress((void**)&Qh,   g_Qh);
    cudaGetSymbolAddress((void**)&Kh,   g_Kh);
    cudaGetSymbolAddress((void**)&Vh,   g_Vh);
    cudaGetSymbolAddress((void**)&AO,   g_AO);
    cudaGetSymbolAddress((void**)&coef, g_coef);

    cudaFuncSetAttribute(gemm_qkv, cudaFuncAttributeMaxDynamicSharedMemorySize,
                         GEMM_SMEM_BYTES);
    cudaFuncSetAttribute(gemm_out, cudaFuncAttributeMaxDynamicSharedMemorySize,
                         GEMM_SMEM_BYTES);
    cudaFuncSetAttribute(attn_tf32, cudaFuncAttributeMaxDynamicSharedMemorySize,
                         ATT_SMEM_BYTES);

    coef_kernel<<<BB, 256>>>(tm, am, coef);

    dim3 gqkv(DM/64, (BB*LL)/128, 3);
    gemm_qkv<<<gqkv, 256, GEMM_SMEM_BYTES>>>(q, k, v, wq, wk, wv,
                                             bq, bk, bv, Qh, Kh, Vh);

    attn_tf32<<<dim3(LL/128, BB*HH), 256, ATT_SMEM_BYTES>>>(Qh, Kh, Vh, tm, am, coef, AO);

    dim3 gg(DM/64, (BB*LL)/128);
    gemm_out<<<gg, 256, GEMM_SMEM_BYTES>>>(AO, wo, bo, out);
}

// round 16
// speedup vs baseline: 1.4641x; 1.4641x over previous
#include <cuda_runtime.h>
#include <cuda_bf16.h>
#include <cstdint>

#define BB 2
#define HH 8
#define LL 2048
#define LT 1024
#define DM 512
#define DH 64

// ---------------- scratch (no allocations allowed) ----------------
__device__ float g_Qh[BB*HH*LL*DH];
__device__ float g_Kh[BB*HH*LL*DH];
__device__ float g_Vh[BB*HH*LL*DH];
__device__ float g_AO[BB*HH*LL*DH];
__device__ float g_coef[BB*LL];

__device__ __forceinline__ uint32_t f2tf32(float x) {
    uint32_t u;
    asm("cvt.rna.tf32.f32 %0, %1;" : "=r"(u) : "f"(x));
    return u;
}

__device__ __forceinline__ void mma_tf32(float d[4], const uint32_t a[4], const uint32_t b[2]) {
    asm volatile(
        "mma.sync.aligned.m16n8k8.row.col.f32.tf32.tf32.f32 "
        "{%0,%1,%2,%3}, {%4,%5,%6,%7}, {%8,%9}, {%0,%1,%2,%3};\n"
        : "+f"(d[0]), "+f"(d[1]), "+f"(d[2]), "+f"(d[3])
        : "r"(a[0]), "r"(a[1]), "r"(a[2]), "r"(a[3]), "r"(b[0]), "r"(b[1]));
}

// ---------------- coef: post-softmax reweighting per (b, pos) ----------------
__global__ void coef_kernel(const float* __restrict__ tm, const float* __restrict__ am,
                            float* __restrict__ coef) {
    __shared__ float red[256];
    __shared__ float s_tl;
    __shared__ float s_al;
    int b = blockIdx.x, tid = threadIdx.x;
    float tl = 0.f, al = 0.f;
    for (int i = tid; i < LT; i += 256) { tl += tm[b*LT + i]; al += am[b*LT + i]; }
    red[tid] = tl; __syncthreads();
    for (int s = 128; s > 0; s >>= 1) { if (tid < s) red[tid] += red[tid + s]; __syncthreads(); }
    if (tid == 0) s_tl = red[0];
    __syncthreads();
    red[tid] = al; __syncthreads();
    for (int s = 128; s > 0; s >>= 1) { if (tid < s) red[tid] += red[tid + s]; __syncthreads(); }
    if (tid == 0) s_al = red[0];
    __syncthreads();
    float tot = s_tl + s_al;
    float twf = tot / (2.f * s_tl);
    float awf = tot / (2.f * s_al);
    for (int i = tid; i < LT; i += 256) {
        coef[b*LL + i]      = tm[b*LT + i] * twf;
        coef[b*LL + LT + i] = am[b*LT + i] * awf;
    }
}

// ---------------- tf32 GEMM core geometry ----------------
// 128x64 block tile, BK=32, 256 threads (8 warps 4x2, warp 32x32).
#define GA_STR 136
#define GB_STR 73
#define GEMM_SMEM_BYTES ((2*32*GA_STR + 2*32*GB_STR) * 4)

// ---------------- merged QKV projection GEMM (blockIdx.z selects q/k/v) --------
__global__ __launch_bounds__(256) void gemm_qkv(
        const float* __restrict__ xq, const float* __restrict__ xk,
        const float* __restrict__ xv,
        const float* __restrict__ wq, const float* __restrict__ wk,
        const float* __restrict__ wv,
        const float* __restrict__ bq, const float* __restrict__ bk,
        const float* __restrict__ bv,
        float* __restrict__ yq, float* __restrict__ yk, float* __restrict__ yv) {
    extern __shared__ uint32_t gsm[];
    uint32_t* As = gsm;                    // [2][32][136]
    uint32_t* Bs = gsm + 2*32*GA_STR;      // [2][32][73]
    int z = blockIdx.z;
    const float* X    = (z == 0) ? xq : (z == 1) ? xk : xv;
    const float* W    = (z == 0) ? wq : (z == 1) ? wk : wv;
    const float* bias = (z == 0) ? bq : (z == 1) ? bk : bv;
    float*       Y    = (z == 0) ? yq : (z == 1) ? yk : yv;

    int tid = threadIdx.x;
    int lane = tid & 31, warp = tid >> 5;
    int gid = lane >> 2, tig = lane & 3;
    int wm0 = (warp >> 1) * 32, wn0 = (warp & 1) * 32;
    int n0 = blockIdx.x * 64, m0 = blockIdx.y * 128;

    float acc[2][4][4];
    #pragma unroll
    for (int mt = 0; mt < 2; mt++)
        #pragma unroll
        for (int nt = 0; nt < 4; nt++)
            #pragma unroll
            for (int r = 0; r < 4; r++) acc[mt][nt][r] = 0.f;

    int ar = tid >> 1, ac = (tid & 1) * 16;
    int br = tid >> 2, bc = (tid & 3) * 8;
    int m = m0 + ar;
    const float* Wp = W + (size_t)(n0 + br)*DM + bc;

    float ra[16], rb[8];
    auto LD = [&](int k0) {
        const float* xp = X + (size_t)m*DM + k0 + ac;
        #pragma unroll
        for (int j = 0; j < 4; j++) {
            float4 v = *reinterpret_cast<const float4*>(xp + 4*j);
            ra[j*4+0] = v.x; ra[j*4+1] = v.y; ra[j*4+2] = v.z; ra[j*4+3] = v.w;
        }
        #pragma unroll
        for (int j = 0; j < 2; j++) {
            float4 v = *reinterpret_cast<const float4*>(Wp + k0 + 4*j);
            rb[j*4+0] = v.x; rb[j*4+1] = v.y; rb[j*4+2] = v.z; rb[j*4+3] = v.w;
        }
    };
    auto ST = [&](int st) {
        #pragma unroll
        for (int j = 0; j < 4; j++)
            #pragma unroll
            for (int e = 0; e < 4; e++)
                As[(size_t)(st*32 + ac + 4*j + e)*GA_STR + ar] = f2tf32(ra[j*4+e]);
        #pragma unroll
        for (int j = 0; j < 2; j++)
            #pragma unroll
            for (int e = 0; e < 4; e++)
                Bs[(size_t)(st*32 + bc + 4*j + e)*GB_STR + br] = f2tf32(rb[j*4+e]);
    };

    LD(0); ST(0); __syncthreads();
    for (int it = 0; it < 16; it++) {
        int st = it & 1;
        if (it < 15) LD((it+1)*32);
        #pragma unroll
        for (int kk = 0; kk < 32; kk += 8) {
            const uint32_t* Ab = As + (size_t)(st*32 + kk + tig)*GA_STR;
            uint32_t af[2][4];
            #pragma unroll
            for (int mt = 0; mt < 2; mt++) {
                int mi = wm0 + mt*16 + gid;
                af[mt][0] = Ab[mi];
                af[mt][1] = Ab[mi + 8];
                af[mt][2] = Ab[4*GA_STR + mi];
                af[mt][3] = Ab[4*GA_STR + mi + 8];
            }
            const uint32_t* Bb = Bs + (size_t)(st*32 + kk + tig)*GB_STR;
            #pragma unroll
            for (int nt = 0; nt < 4; nt++) {
                int ni = wn0 + nt*8 + gid;
                uint32_t bf[2] = { Bb[ni], Bb[4*GB_STR + ni] };
                mma_tf32(acc[0][nt], af[0], bf);
                mma_tf32(acc[1][nt], af[1], bf);
            }
        }
        if (it < 15) ST(st ^ 1);
        __syncthreads();
    }

    // scatter into [B,H,L,Dh]
    #pragma unroll
    for (int mt = 0; mt < 2; mt++) {
        #pragma unroll
        for (int nt = 0; nt < 4; nt++) {
            int r0 = m0 + wm0 + mt*16 + gid;
            int c0 = n0 + wn0 + nt*8 + 2*tig;
            float b0 = bias[c0], b1 = bias[c0+1];
            float2 v0 = make_float2(acc[mt][nt][0] + b0, acc[mt][nt][1] + b1);
            float2 v1 = make_float2(acc[mt][nt][2] + b0, acc[mt][nt][3] + b1);
            int bb = r0 >> 11, ll = r0 & 2047;
            int h = c0 >> 6, dd = c0 & 63;
            float* yp = Y + (((size_t)(bb*HH + h)*LL + ll)*DH + dd);
            *reinterpret_cast<float2*>(yp)        = v0;
            *reinterpret_cast<float2*>(yp + 8*DH) = v1;
        }
    }
}

// ---------------- output projection GEMM (gather from [B,H,L,Dh]) --------------
__global__ __launch_bounds__(256) void gemm_out(const float* __restrict__ X,
        const float* __restrict__ W, const float* __restrict__ bias,
        float* __restrict__ Y) {
    extern __shared__ uint32_t gsm[];
    uint32_t* As = gsm;
    uint32_t* Bs = gsm + 2*32*GA_STR;
    int tid = threadIdx.x;
    int lane = tid & 31, warp = tid >> 5;
    int gid = lane >> 2, tig = lane & 3;
    int wm0 = (warp >> 1) * 32, wn0 = (warp & 1) * 32;
    int n0 = blockIdx.x * 64, m0 = blockIdx.y * 128;

    float acc[2][4][4];
    #pragma unroll
    for (int mt = 0; mt < 2; mt++)
        #pragma unroll
        for (int nt = 0; nt < 4; nt++)
            #pragma unroll
            for (int r = 0; r < 4; r++) acc[mt][nt][r] = 0.f;

    int ar = tid >> 1, ac = (tid & 1) * 16;
    int br = tid >> 2, bc = (tid & 3) * 8;
    int m = m0 + ar;
    int mb = m >> 11, ml = m & 2047;
    const float* Wp = W + (size_t)(n0 + br)*DM + bc;

    float ra[16], rb[8];
    auto LD = [&](int k0) {
        int kk4 = k0 + ac;   // multiple of 16; 16-elem span never crosses head
        const float* xp = X + (((size_t)(mb*HH + (kk4 >> 6))*LL + ml)*DH + (kk4 & 63));
        #pragma unroll
        for (int j = 0; j < 4; j++) {
            float4 v = *reinterpret_cast<const float4*>(xp + 4*j);
            ra[j*4+0] = v.x; ra[j*4+1] = v.y; ra[j*4+2] = v.z; ra[j*4+3] = v.w;
        }
        #pragma unroll
        for (int j = 0; j < 2; j++) {
            float4 v = *reinterpret_cast<const float4*>(Wp + k0 + 4*j);
            rb[j*4+0] = v.x; rb[j*4+1] = v.y; rb[j*4+2] = v.z; rb[j*4+3] = v.w;
        }
    };
    auto ST = [&](int st) {
        #pragma unroll
        for (int j = 0; j < 4; j++)
            #pragma unroll
            for (int e = 0; e < 4; e++)
                As[(size_t)(st*32 + ac + 4*j + e)*GA_STR + ar] = f2tf32(ra[j*4+e]);
        #pragma unroll
        for (int j = 0; j < 2; j++)
            #pragma unroll
            for (int e = 0; e < 4; e++)
                Bs[(size_t)(st*32 + bc + 4*j + e)*GB_STR + br] = f2tf32(rb[j*4+e]);
    };

    LD(0); ST(0); __syncthreads();
    for (int it = 0; it < 16; it++) {
        int st = it & 1;
        if (it < 15) LD((it+1)*32);
        #pragma unroll
        for (int kk = 0; kk < 32; kk += 8) {
            const uint32_t* Ab = As + (size_t)(st*32 + kk + tig)*GA_STR;
            uint32_t af[2][4];
            #pragma unroll
            for (int mt = 0; mt < 2; mt++) {
                int mi = wm0 + mt*16 + gid;
                af[mt][0] = Ab[mi];
                af[mt][1] = Ab[mi + 8];
                af[mt][2] = Ab[4*GA_STR + mi];
                af[mt][3] = Ab[4*GA_STR + mi + 8];
            }
            const uint32_t* Bb = Bs + (size_t)(st*32 + kk + tig)*GB_STR;
            #pragma unroll
            for (int nt = 0; nt < 4; nt++) {
                int ni = wn0 + nt*8 + gid;
                uint32_t bf[2] = { Bb[ni], Bb[4*GB_STR + ni] };
                mma_tf32(acc[0][nt], af[0], bf);
                mma_tf32(acc[1][nt], af[1], bf);
            }
        }
        if (it < 15) ST(st ^ 1);
        __syncthreads();
    }

    #pragma unroll
    for (int mt = 0; mt < 2; mt++) {
        #pragma unroll
        for (int nt = 0; nt < 4; nt++) {
            int r0 = m0 + wm0 + mt*16 + gid;
            int c0 = n0 + wn0 + nt*8 + 2*tig;
            float b0 = bias[c0], b1 = bias[c0+1];
            *reinterpret_cast<float2*>(Y + (size_t)r0*DM + c0) =
                make_float2(acc[mt][nt][0] + b0, acc[mt][nt][1] + b1);
            *reinterpret_cast<float2*>(Y + (size_t)(r0+8)*DM + c0) =
                make_float2(acc[mt][nt][2] + b0, acc[mt][nt][3] + b1);
        }
    }
}

// ---------------- tf32 flash attention, single-buffer K/V + reg prefetch --------
// grid (L/128, B*H), 256 threads. Warp w owns q rows [w*16, w*16+16). 64-key tiles.
// SMEM-P datapath (round-10, measured good). K/V single-buffered; tile i+1 held in
// registers during compute, stored after a barrier. SMEM = 71 KB -> 2 CTA/SM if regs<=128.
#define KS_STR 72
#define PS_STR 68
#define ATT_SMEM_BYTES ((64*KS_STR + 64*KS_STR + 128*PS_STR + 256) * 4)

__global__ __launch_bounds__(256) void attn_tf32(const float* __restrict__ Qh,
        const float* __restrict__ Kh, const float* __restrict__ Vh,
        const float* __restrict__ tm, const float* __restrict__ am,
        const float* __restrict__ coef, float* __restrict__ Out) {
    extern __shared__ uint32_t smu[];
    uint32_t* Kd  = smu;                       // [d=64][col 72]
    uint32_t* Vd  = smu + 64*KS_STR;           // [kk=64][d 72]
    uint32_t* PsB = Vd  + 64*KS_STR;           // [q 128][kk 68]
    float* kmzS = (float*)(PsB + 128*PS_STR);  // [2][64] (masks stay double-buffered)
    float* kcfS = kmzS + 128;                  // [2][64]
#define KS(d,c) Kd[(size_t)(d)*KS_STR + (c)]
#define VS(r,c) Vd[(size_t)(r)*KS_STR + (c)]
#define PS(r,c) PsB[(size_t)(r)*PS_STR + (c)]

    int tid = threadIdx.x;
    int lane = tid & 31, warp = tid >> 5;
    int gid = lane >> 2, tig = lane & 3;
    int bh = blockIdx.y, b = bh >> 3;
    int q0 = blockIdx.x * 128;
    int qw = q0 + warp * 16;

    // Q fragments in registers (pre-scaled by 1/sqrt(64))
    uint32_t qf[8][4];
    const float* Qb = Qh + ((size_t)bh*LL + qw)*DH;
    #pragma unroll
    for (int kt = 0; kt < 8; kt++) {
        int c = kt*8 + tig;
        qf[kt][0] = f2tf32(Qb[(size_t)gid*DH     + c    ] * 0.125f);
        qf[kt][1] = f2tf32(Qb[(size_t)(gid+8)*DH + c    ] * 0.125f);
        qf[kt][2] = f2tf32(Qb[(size_t)gid*DH     + c + 4] * 0.125f);
        qf[kt][3] = f2tf32(Qb[(size_t)(gid+8)*DH + c + 4] * 0.125f);
    }
    int p0 = qw + gid, p1 = qw + gid + 8;
    float qz0 = (p0 < LT) ? tm[b*LT + p0] : am[b*LT + p0 - LT];
    float qz1 = (p1 < LT) ? tm[b*LT + p1] : am[b*LT + p1 - LT];

    float m0r = -1e30f, m1r = -1e30f, l0r = 0.f, l1r = 0.f;
    float o[8][4];
    #pragma unroll
    for (int nt = 0; nt < 8; nt++)
        #pragma unroll
        for (int r = 0; r < 4; r++) o[nt][r] = 0.f;

    int kcol = tid & 63, cgrp = (tid >> 6) * 16;   // K loader (transposed store)
    int vr = tid >> 2, vc = (tid & 3) * 16;        // V loader (direct store)
    int prow = warp*16 + gid;
    const float* Kbase = Kh + (size_t)bh*LL*DH;
    const float* Vbase = Vh + (size_t)bh*LL*DH;

    float rbuf[16];          // reused for K-prefetch then V-prefetch
    float rmv = 0.f, rcv = 0.f;

    auto LDK = [&](int t0) {
        const float* p = Kbase + (size_t)(t0 + kcol)*DH + cgrp;
        #pragma unroll
        for (int j = 0; j < 4; j++) {
            float4 v = *reinterpret_cast<const float4*>(p + 4*j);
            rbuf[j*4+0] = v.x; rbuf[j*4+1] = v.y; rbuf[j*4+2] = v.z; rbuf[j*4+3] = v.w;
        }
    };
    auto STK = [&]() {
        #pragma unroll
        for (int j = 0; j < 4; j++)
            #pragma unroll
            for (int e = 0; e < 4; e++)
                KS(cgrp + 4*j + e, kcol) = f2tf32(rbuf[j*4+e]);
    };
    auto LDV = [&](int t0) {
        const float* p = Vbase + (size_t)(t0 + vr)*DH + vc;
        #pragma unroll
        for (int j = 0; j < 4; j++) {
            float4 v = *reinterpret_cast<const float4*>(p + 4*j);
            rbuf[j*4+0] = v.x; rbuf[j*4+1] = v.y; rbuf[j*4+2] = v.z; rbuf[j*4+3] = v.w;
        }
    };
    auto STV = [&]() {
        uint4* vd = reinterpret_cast<uint4*>(&VS(vr, vc));
        #pragma unroll
        for (int j = 0; j < 4; j++) {
            uint4 w;
            w.x = f2tf32(rbuf[j*4+0]); w.y = f2tf32(rbuf[j*4+1]);
            w.z = f2tf32(rbuf[j*4+2]); w.w = f2tf32(rbuf[j*4+3]);
            vd[j] = w;
        }
    };
    auto LDM = [&](int t0) {
        if (tid < 64) {
            int pos = t0 + tid;
            rmv = (pos < LT) ? tm[b*LT + pos] : am[b*LT + pos - LT];
            rcv = coef[b*LL + pos];
        }
    };
    auto STM = [&](int half) {
        if (tid < 64) { kmzS[half*64 + tid] = rmv; kcfS[half*64 + tid] = rcv; }
    };

    // prologue: fill tile 0
    LDK(0); STK(); LDV(0); STV(); LDM(0); STM(0);
    __syncthreads();

    for (int i = 0; i < 32; i++) {
        int mst = i & 1;                // mask buffer half for THIS tile
        bool pf = (i < 31);
        int t1 = (i + 1) * 64;
        if (pf) { LDK(t1); LDM(t1); }

        // S = Q @ K^T  (16 x 64 per warp)  -- reads K buffer
        float s[8][4];
        #pragma unroll
        for (int nt = 0; nt < 8; nt++)
            #pragma unroll
            for (int r = 0; r < 4; r++) s[nt][r] = 0.f;
        #pragma unroll
        for (int kt = 0; kt < 8; kt++) {
            #pragma unroll
            for (int nt = 0; nt < 8; nt++) {
                uint32_t bf[2];
                bf[0] = KS(kt*8+tig,   nt*8+gid);
                bf[1] = KS(kt*8+tig+4, nt*8+gid);
                mma_tf32(s[nt], qf[kt], bf);
            }
        }
        __syncthreads();                 // barrier 1: all warps done reading K
        if (pf) { STK(); STM(mst ^ 1); } // overwrite K buffer with tile i+1

        // dual mask (this tile's masks live in half mst)
        const float* kmp = kmzS + mst*64;
        const float* kcp = kcfS + mst*64;
        #pragma unroll
        for (int nt = 0; nt < 8; nt++) {
            int c = nt*8 + 2*tig;
            float km0 = kmp[c], km1 = kmp[c+1];
            if (qz0 == 0.f || km0 == 0.f) s[nt][0] = -1e4f;
            if (qz0 == 0.f || km1 == 0.f) s[nt][1] = -1e4f;
            if (qz1 == 0.f || km0 == 0.f) s[nt][2] = -1e4f;
            if (qz1 == 0.f || km1 == 0.f) s[nt][3] = -1e4f;
        }

        // online softmax (rows gid / gid+8; quad lanes share a row)
        float rm0 = -1e30f, rm1 = -1e30f;
        #pragma unroll
        for (int nt = 0; nt < 8; nt++) {
            rm0 = fmaxf(rm0, fmaxf(s[nt][0], s[nt][1]));
            rm1 = fmaxf(rm1, fmaxf(s[nt][2], s[nt][3]));
        }
        rm0 = fmaxf(rm0, __shfl_xor_sync(0xffffffffu, rm0, 1));
        rm0 = fmaxf(rm0, __shfl_xor_sync(0xffffffffu, rm0, 2));
        rm1 = fmaxf(rm1, __shfl_xor_sync(0xffffffffu, rm1, 1));
        rm1 = fmaxf(rm1, __shfl_xor_sync(0xffffffffu, rm1, 2));
        float mn0 = fmaxf(m0r, rm0), mn1 = fmaxf(m1r, rm1);
        float rs0 = 0.f, rs1 = 0.f;
        #pragma unroll
        for (int nt = 0; nt < 8; nt++) {
            s[nt][0] = __expf(s[nt][0] - mn0);
            s[nt][1] = __expf(s[nt][1] - mn0);
            s[nt][2] = __expf(s[nt][2] - mn1);
            s[nt][3] = __expf(s[nt][3] - mn1);
            rs0 += s[nt][0] + s[nt][1];
            rs1 += s[nt][2] + s[nt][3];
        }
        rs0 += __shfl_xor_sync(0xffffffffu, rs0, 1);
        rs0 += __shfl_xor_sync(0xffffffffu, rs0, 2);
        rs1 += __shfl_xor_sync(0xffffffffu, rs1, 1);
        rs1 += __shfl_xor_sync(0xffffffffu, rs1, 2);
        float a0 = __expf(m0r - mn0), a1 = __expf(m1r - mn1);
        l0r = l0r*a0 + rs0; l1r = l1r*a1 + rs1;
        m0r = mn0; m1r = mn1;
        #pragma unroll
        for (int nt = 0; nt < 8; nt++) {
            o[nt][0] *= a0; o[nt][1] *= a0;
            o[nt][2] *= a1; o[nt][3] *= a1;
        }

        if (pf) LDV(t1);   // rbuf free again (STK done); overlap with PV below

        // P * coef -> SMEM (warp-private region)
        #pragma unroll
        for (int nt = 0; nt < 8; nt++) {
            int c = nt*8 + 2*tig;
            float c0 = kcp[c], c1 = kcp[c+1];
            uint2 v0; v0.x = f2tf32(s[nt][0]*c0); v0.y = f2tf32(s[nt][1]*c1);
            uint2 v1; v1.x = f2tf32(s[nt][2]*c0); v1.y = f2tf32(s[nt][3]*c1);
            *reinterpret_cast<uint2*>(&PS(prow,   c)) = v0;
            *reinterpret_cast<uint2*>(&PS(prow+8, c)) = v1;
        }
        __syncwarp();

        // O += P @ V  -- reads V buffer
        #pragma unroll
        for (int kt = 0; kt < 8; kt++) {
            uint32_t af[4];
            af[0] = PS(prow,   kt*8+tig);
            af[1] = PS(prow+8, kt*8+tig);
            af[2] = PS(prow,   kt*8+tig+4);
            af[3] = PS(prow+8, kt*8+tig+4);
            #pragma unroll
            for (int nt = 0; nt < 8; nt++) {
                uint32_t bf[2];
                bf[0] = VS(kt*8+tig,   nt*8+gid);
                bf[1] = VS(kt*8+tig+4, nt*8+gid);
                mma_tf32(o[nt], af, bf);
            }
        }
        __syncthreads();                 // barrier 2: all done reading V; K store visible
        if (pf) STV();                   // overwrite V buffer with tile i+1
    }

    float il0 = 1.f / l0r, il1 = 1.f / l1r;
    float* ob = Out + ((size_t)bh*LL + qw)*DH;
    #pragma unroll
    for (int nt = 0; nt < 8; nt++) {
        int c = nt*8 + 2*tig;
        *reinterpret_cast<float2*>(ob + (size_t)gid*DH + c) =
            make_float2(o[nt][0]*il0, o[nt][1]*il0);
        *reinterpret_cast<float2*>(ob + (size_t)(gid+8)*DH + c) =
            make_float2(o[nt][2]*il1, o[nt][3]*il1);
    }
}

extern "C" void kernel_launch(void* const* d_in, const int* in_sizes, int n_in,
                              void* d_out, int out_size) {
    const float* q  = (const float*)d_in[0];
    const float* k  = (const float*)d_in[1];
    const float* v  = (const float*)d_in[2];
    const float* tm = (const float*)d_in[3];
    const float* am = (const float*)d_in[4];
    // d_in[5] = n_head (constant 8)
    const float* wq = (const float*)d_in[6];
    const float* bq = (const float*)d_in[7];
    const float* wk = (const float*)d_in[8];
    const float* bk = (const float*)d_in[9];
    const float* wv = (const float*)d_in[10];
    const float* bv = (const float*)d_in[11];
    const float* wo = (const float*)d_in[12];
    const float* bo = (const float*)d_in[13];
    float* out = (float*)d_out;

    float *Qh, *Kh, *Vh, *AO, *coef;
    cudaGetSymbolAddress((void**)&Qh,   g_Qh);
    cudaGetSymbolAddress((void**)&Kh,   g_Kh);
    cudaGetSymbolAddress((void**)&Vh,   g_Vh);
    cudaGetSymbolAddress((void**)&AO,   g_AO);
    cudaGetSymbolAddress((void**)&coef, g_coef);

    cudaFuncSetAttribute(gemm_qkv, cudaFuncAttributeMaxDynamicSharedMemorySize,
                         GEMM_SMEM_BYTES);
    cudaFuncSetAttribute(gemm_out, cudaFuncAttributeMaxDynamicSharedMemorySize,
                         GEMM_SMEM_BYTES);
    cudaFuncSetAttribute(attn_tf32, cudaFuncAttributeMaxDynamicSharedMemorySize,
                         ATT_SMEM_BYTES);

    coef_kernel<<<BB, 256>>>(tm, am, coef);

    dim3 gqkv(DM/64, (BB*LL)/128, 3);
    gemm_qkv<<<gqkv, 256, GEMM_SMEM_BYTES>>>(q, k, v, wq, wk, wv,
                                             bq, bk, bv, Qh, Kh, Vh);

    attn_tf32<<<dim3(LL/128, BB*HH), 256, ATT_SMEM_BYTES>>>(Qh, Kh, Vh, tm, am, coef, AO);

    dim3 gg(DM/64, (BB*LL)/128);
    gemm_out<<<gg, 256, GEMM_SMEM_BYTES>>>(AO, wo, bo, out);
}